// round 2
// baseline (speedup 1.0000x reference)
#include <cuda_runtime.h>
#include <math.h>

#define Bb     16
#define Hh     56
#define Wd     56
#define Nn     3136
#define Dd     256
#define HEADS  8
#define HD     32
#define WIN    7
#define WIN2   49
#define NWH    8
#define NW     64
#define DISP   3
#define FF     1024
#define CPBH   512
#define EPSLN  1e-5f
#define MROWS  50176   // B * N

// ---------------- device scratch (no allocs allowed) ----------------
__device__ float g_xm  [MROWS * Dd];       // 51.4 MB
__device__ float g_qkv [MROWS * 3 * Dd];   // 154 MB
__device__ float g_attn[MROWS * Dd];       // 51.4 MB (also ffn2 tmp)
__device__ float g_ffh [MROWS * FF];       // 205 MB (also oproj tmp)
__device__ float g_cpb [HEADS * WIN2 * WIN2];

// ---------------- add spatial position embedding ----------------
__global__ void add_spe_kernel(const float* __restrict__ x,
                               const float* __restrict__ spe,
                               float* __restrict__ out, int n4) {
    int i = blockIdx.x * blockDim.x + threadIdx.x;
    if (i < n4) {
        float4 a = ((const float4*)x)[i];
        float4 b = ((const float4*)spe)[i];
        a.x += b.x; a.y += b.y; a.z += b.z; a.w += b.w;
        ((float4*)out)[i] = a;
    }
}

// ---------------- CPB MLP: relu(REL@cw1+cb1)@cw2+cb2 -> (8,49,49) ----------------
__global__ void cpb_kernel(const float* __restrict__ cw1, const float* __restrict__ cb1,
                           const float* __restrict__ cw2, const float* __restrict__ cb2,
                           float* __restrict__ cpb) {
    int p = blockIdx.x;                 // pair (i,j), 2401 blocks
    int i = p / WIN2, j = p % WIN2;
    float dy = (float)(j / WIN - i / WIN);
    float dx = (float)(j % WIN - i % WIN);
    float r0 = ((dy > 0.f) - (dy < 0.f)) * log1pf(fabsf(dy));
    float r1 = ((dx > 0.f) - (dx < 0.f)) * log1pf(fabsf(dx));

    int tid = threadIdx.x;              // 256 threads, 2 hidden units each
    int c0 = tid, c1 = tid + 256;
    float h0 = fmaxf(r0 * cw1[c0] + r1 * cw1[CPBH + c0] + cb1[c0], 0.f);
    float h1 = fmaxf(r0 * cw1[c1] + r1 * cw1[CPBH + c1] + cb1[c1], 0.f);

    __shared__ float red[256];
    for (int h = 0; h < HEADS; h++) {
        float part = h0 * cw2[c0 * HEADS + h] + h1 * cw2[c1 * HEADS + h];
        red[tid] = part;
        __syncthreads();
        for (int s = 128; s > 0; s >>= 1) {
            if (tid < s) red[tid] += red[tid + s];
            __syncthreads();
        }
        if (tid == 0) cpb[h * (WIN2 * WIN2) + p] = red[0] + cb2[h];
        __syncthreads();
    }
}

// ---------------- SGEMM 128x64x16, 8x4 microtile, 256 threads ----------------
// ACT: 0 none, 1 exact GELU. GATHER: roll input rows by (+3,+3) (shifted-window qkv).
template<int ACT, bool GATHER>
__global__ void __launch_bounds__(256)
sgemm_kernel(const float* __restrict__ A, const float* __restrict__ Wt,
             const float* __restrict__ bias, float* __restrict__ C,
             int N, int K) {
    __shared__ float sa[16][132];
    __shared__ float sb[16][68];

    const int tid = threadIdx.x;
    const int tx = tid & 15, ty = tid >> 4;
    const int bm = blockIdx.y * 128;
    const int bn = blockIdx.x * 64;

    // Precompute (possibly gathered) A row base pointers for the 2 float4 loads.
    const float* arow[2];
    int ac4[2];
    #pragma unroll
    for (int l = 0; l < 2; l++) {
        int f = tid + l * 256;
        int r = f >> 2; ac4[l] = f & 3;
        int gm = bm + r;
        if (GATHER) {
            int b = gm / Nn, rem = gm - b * Nn;
            int h = rem / Wd, w = rem - h * Wd;
            h = (h + DISP) % Hh; w = (w + DISP) % Wd;
            gm = b * Nn + h * Wd + w;
        }
        arow[l] = A + (size_t)gm * K;
    }
    const int brow = tid >> 4, bc4 = tid & 15;

    float acc[8][4];
    #pragma unroll
    for (int i = 0; i < 8; i++)
        #pragma unroll
        for (int j = 0; j < 4; j++) acc[i][j] = 0.f;

    for (int kt = 0; kt < K; kt += 16) {
        #pragma unroll
        for (int l = 0; l < 2; l++) {
            int f = tid + l * 256;
            int r = f >> 2;
            float4 v = *(const float4*)(arow[l] + kt + ac4[l] * 4);
            int c = ac4[l] * 4;
            sa[c + 0][r] = v.x; sa[c + 1][r] = v.y;
            sa[c + 2][r] = v.z; sa[c + 3][r] = v.w;
        }
        *(float4*)&sb[brow][bc4 * 4] =
            *(const float4*)(Wt + (size_t)(kt + brow) * N + bn + bc4 * 4);
        __syncthreads();

        #pragma unroll
        for (int kk = 0; kk < 16; kk++) {
            float af[8], bf[4];
            *(float4*)&af[0] = *(const float4*)&sa[kk][ty * 8];
            *(float4*)&af[4] = *(const float4*)&sa[kk][ty * 8 + 4];
            *(float4*)&bf[0] = *(const float4*)&sb[kk][tx * 4];
            #pragma unroll
            for (int i = 0; i < 8; i++)
                #pragma unroll
                for (int j = 0; j < 4; j++)
                    acc[i][j] += af[i] * bf[j];
        }
        __syncthreads();
    }

    float bv[4] = {0.f, 0.f, 0.f, 0.f};
    if (bias) {
        #pragma unroll
        for (int j = 0; j < 4; j++) bv[j] = bias[bn + tx * 4 + j];
    }
    #pragma unroll
    for (int i = 0; i < 8; i++) {
        int gr = bm + ty * 8 + i;
        float4 o;
        float vals[4];
        #pragma unroll
        for (int j = 0; j < 4; j++) {
            float v = acc[i][j] + bv[j];
            if (ACT == 1) v = v * 0.5f * (1.f + erff(v * 0.7071067811865476f));
            vals[j] = v;
        }
        o.x = vals[0]; o.y = vals[1]; o.z = vals[2]; o.w = vals[3];
        *(float4*)(C + (size_t)gr * N + bn + tx * 4) = o;
    }
}

// ---------------- window attention: one block per (window, head, batch) ----------------
__global__ void __launch_bounds__(256)
attn_kernel(const float* __restrict__ qkv, const float* __restrict__ tau,
            const float* __restrict__ cpb, float* __restrict__ out, int shifted) {
    __shared__ float sq[64 * 33];
    __shared__ float sk[64 * 33];
    __shared__ float sv[49 * 33];
    __shared__ float sd[64 * 52];

    const int wi   = blockIdx.x;        // 0..63
    const int head = blockIdx.y;        // 0..7
    const int b    = blockIdx.z;        // 0..15
    const int wh = wi >> 3, ww = wi & 7;
    const int tid = threadIdx.x;

    // load q,k,v (49x32 each); zero-pad q,k rows 49..63
    for (int e = tid; e < 64 * 32; e += 256) {
        int r = e >> 5, d = e & 31;
        if (r < WIN2) {
            int i = r / WIN, j = r % WIN;
            int m = b * Nn + (wh * WIN + i) * Wd + (ww * WIN + j);
            const float* base = qkv + (size_t)m * 768 + head * HD + d;
            sq[r * 33 + d] = base[0];
            sk[r * 33 + d] = base[256];
            sv[r * 33 + d] = base[512];
        } else {
            sq[r * 33 + d] = 0.f;
            sk[r * 33 + d] = 0.f;
        }
    }
    __syncthreads();

    // l2-normalize q and k rows
    for (int t = tid; t < 2 * WIN2; t += 256) {
        float* row = (t < WIN2) ? (sq + t * 33) : (sk + (t - WIN2) * 33);
        float s = 0.f;
        #pragma unroll
        for (int d = 0; d < HD; d++) s += row[d] * row[d];
        float inv = 1.f / fmaxf(sqrtf(s), 1e-12f);
        #pragma unroll
        for (int d = 0; d < HD; d++) row[d] *= inv;
    }
    __syncthreads();

    const float tscale = 1.f / fmaxf(tau[head], 0.01f);
    const int tx = tid & 15, ty = tid >> 4;

    // dots = qn @ kn^T, 4x4 microtile on 16x16 threads
    float acc[4][4];
    #pragma unroll
    for (int u = 0; u < 4; u++)
        #pragma unroll
        for (int v = 0; v < 4; v++) acc[u][v] = 0.f;
    #pragma unroll
    for (int kk = 0; kk < HD; kk++) {
        float a[4], bb[4];
        #pragma unroll
        for (int u = 0; u < 4; u++) a[u]  = sq[(ty + u * 16) * 33 + kk];
        #pragma unroll
        for (int v = 0; v < 4; v++) bb[v] = sk[(tx + v * 16) * 33 + kk];
        #pragma unroll
        for (int u = 0; u < 4; u++)
            #pragma unroll
            for (int v = 0; v < 4; v++) acc[u][v] += a[u] * bb[v];
    }
    // scale + cpb + shift masks
    #pragma unroll
    for (int u = 0; u < 4; u++) {
        int i = ty + u * 16;
        if (i >= WIN2) continue;
        #pragma unroll
        for (int v = 0; v < 4; v++) {
            int j = tx + v * 16;
            if (j >= WIN2) continue;
            float val = acc[u][v] * tscale + cpb[head * (WIN2 * WIN2) + i * WIN2 + j];
            if (shifted) {
                if (wh == NWH - 1 && ((i >= 28) != (j >= 28))) val = -1e30f;
                if (ww == NWH - 1 && (((i % WIN) >= 4) != ((j % WIN) >= 4))) val = -1e30f;
            }
            sd[i * 52 + j] = val;
        }
    }
    __syncthreads();

    // softmax: one warp per row
    const int lane = tid & 31, wrp = tid >> 5;
    for (int r = wrp; r < WIN2; r += 8) {
        float v0 = sd[r * 52 + lane];
        float v1 = (lane + 32 < WIN2) ? sd[r * 52 + lane + 32] : -3e38f;
        float mx = fmaxf(v0, v1);
        #pragma unroll
        for (int o = 16; o > 0; o >>= 1) mx = fmaxf(mx, __shfl_xor_sync(~0u, mx, o));
        float e0 = __expf(v0 - mx);
        float e1 = (lane + 32 < WIN2) ? __expf(v1 - mx) : 0.f;
        float s = e0 + e1;
        #pragma unroll
        for (int o = 16; o > 0; o >>= 1) s += __shfl_xor_sync(~0u, s, o);
        float inv = 1.f / s;
        sd[r * 52 + lane] = e0 * inv;
        if (lane + 32 < WIN2) sd[r * 52 + lane + 32] = e1 * inv;
    }
    __syncthreads();

    // out = attn @ v, 4x2 microtile
    float o2[4][2];
    #pragma unroll
    for (int u = 0; u < 4; u++) { o2[u][0] = 0.f; o2[u][1] = 0.f; }
    for (int j = 0; j < WIN2; j++) {
        float p[4];
        #pragma unroll
        for (int u = 0; u < 4; u++) p[u] = sd[(ty + u * 16) * 52 + j];
        float v0 = sv[j * 33 + tx * 2];
        float v1 = sv[j * 33 + tx * 2 + 1];
        #pragma unroll
        for (int u = 0; u < 4; u++) {
            o2[u][0] += p[u] * v0;
            o2[u][1] += p[u] * v1;
        }
    }
    #pragma unroll
    for (int u = 0; u < 4; u++) {
        int i = ty + u * 16;
        if (i < WIN2) {
            int ii = i / WIN, jj = i % WIN;
            int m = b * Nn + (wh * WIN + ii) * Wd + (ww * WIN + jj);
            float* dst = out + (size_t)m * Dd + head * HD + tx * 2;
            dst[0] = o2[u][0];
            dst[1] = o2[u][1];
        }
    }
}

// ---------------- LN + residual (one warp per row), optional roll-back gather ----------------
__global__ void ln_residual_kernel(const float* __restrict__ A, const float* __restrict__ g,
                                   const float* __restrict__ be, float* __restrict__ xm,
                                   int gather) {
    int row = blockIdx.x * 8 + (threadIdx.x >> 5);
    int lane = threadIdx.x & 31;
    int src = row;
    if (gather) {
        int b = row / Nn, rem = row % Nn;
        int h = rem / Wd, w = rem % Wd;
        src = b * Nn + ((h + Hh - DISP) % Hh) * Wd + ((w + Wd - DISP) % Wd);
    }
    const float4* a4 = (const float4*)(A + (size_t)src * Dd);
    float4 v0 = a4[lane], v1 = a4[lane + 32];
    float s  = v0.x + v0.y + v0.z + v0.w + v1.x + v1.y + v1.z + v1.w;
    float s2 = v0.x*v0.x + v0.y*v0.y + v0.z*v0.z + v0.w*v0.w
             + v1.x*v1.x + v1.y*v1.y + v1.z*v1.z + v1.w*v1.w;
    #pragma unroll
    for (int o = 16; o > 0; o >>= 1) {
        s  += __shfl_xor_sync(~0u, s, o);
        s2 += __shfl_xor_sync(~0u, s2, o);
    }
    float mean = s * (1.f / Dd);
    float var  = s2 * (1.f / Dd) - mean * mean;
    float inv  = rsqrtf(var + EPSLN);

    float4 g0 = ((const float4*)g)[lane],  g1 = ((const float4*)g)[lane + 32];
    float4 b0 = ((const float4*)be)[lane], b1 = ((const float4*)be)[lane + 32];
    float4* x4 = (float4*)(xm + (size_t)row * Dd);
    float4 r0 = x4[lane], r1 = x4[lane + 32];
    r0.x += (v0.x - mean) * inv * g0.x + b0.x;
    r0.y += (v0.y - mean) * inv * g0.y + b0.y;
    r0.z += (v0.z - mean) * inv * g0.z + b0.z;
    r0.w += (v0.w - mean) * inv * g0.w + b0.w;
    r1.x += (v1.x - mean) * inv * g1.x + b1.x;
    r1.y += (v1.y - mean) * inv * g1.y + b1.y;
    r1.z += (v1.z - mean) * inv * g1.z + b1.z;
    r1.w += (v1.w - mean) * inv * g1.w + b1.w;
    x4[lane] = r0; x4[lane + 32] = r1;
}

// ---------------- final LN -> output ----------------
__global__ void ln_final_kernel(const float* __restrict__ A, const float* __restrict__ g,
                                const float* __restrict__ be, float* __restrict__ out) {
    int row = blockIdx.x * 8 + (threadIdx.x >> 5);
    int lane = threadIdx.x & 31;
    const float4* a4 = (const float4*)(A + (size_t)row * Dd);
    float4 v0 = a4[lane], v1 = a4[lane + 32];
    float s  = v0.x + v0.y + v0.z + v0.w + v1.x + v1.y + v1.z + v1.w;
    float s2 = v0.x*v0.x + v0.y*v0.y + v0.z*v0.z + v0.w*v0.w
             + v1.x*v1.x + v1.y*v1.y + v1.z*v1.z + v1.w*v1.w;
    #pragma unroll
    for (int o = 16; o > 0; o >>= 1) {
        s  += __shfl_xor_sync(~0u, s, o);
        s2 += __shfl_xor_sync(~0u, s2, o);
    }
    float mean = s * (1.f / Dd);
    float var  = s2 * (1.f / Dd) - mean * mean;
    float inv  = rsqrtf(var + EPSLN);
    float4 g0 = ((const float4*)g)[lane],  g1 = ((const float4*)g)[lane + 32];
    float4 b0 = ((const float4*)be)[lane], b1 = ((const float4*)be)[lane + 32];
    float4 o0, o1;
    o0.x = (v0.x - mean) * inv * g0.x + b0.x;
    o0.y = (v0.y - mean) * inv * g0.y + b0.y;
    o0.z = (v0.z - mean) * inv * g0.z + b0.z;
    o0.w = (v0.w - mean) * inv * g0.w + b0.w;
    o1.x = (v1.x - mean) * inv * g1.x + b1.x;
    o1.y = (v1.y - mean) * inv * g1.y + b1.y;
    o1.z = (v1.z - mean) * inv * g1.z + b1.z;
    o1.w = (v1.w - mean) * inv * g1.w + b1.w;
    float4* out4 = (float4*)(out + (size_t)row * Dd);
    out4[lane] = o0; out4[lane + 32] = o1;
}

// ---------------- launch ----------------
extern "C" void kernel_launch(void* const* d_in, const int* in_sizes, int n_in,
                              void* d_out, int out_size) {
    const float* x    = (const float*)d_in[0];
    const float* spe  = (const float*)d_in[1];
    const float* qkvw = (const float*)d_in[2];
    const float* tau  = (const float*)d_in[3];
    const float* cw1  = (const float*)d_in[4];
    const float* cb1  = (const float*)d_in[5];
    const float* cw2  = (const float*)d_in[6];
    const float* cb2  = (const float*)d_in[7];
    const float* ow   = (const float*)d_in[8];
    const float* ob   = (const float*)d_in[9];
    const float* ln1g = (const float*)d_in[10];
    const float* ln1b = (const float*)d_in[11];
    const float* fw1  = (const float*)d_in[12];
    const float* fb1  = (const float*)d_in[13];
    const float* fw2  = (const float*)d_in[14];
    const float* fb2  = (const float*)d_in[15];
    const float* ln2g = (const float*)d_in[16];
    const float* ln2b = (const float*)d_in[17];
    const float* ng   = (const float*)d_in[18];
    const float* nb   = (const float*)d_in[19];
    float* out = (float*)d_out;

    float *xm, *qkv, *attn, *ffh, *cpb;
    cudaGetSymbolAddress((void**)&xm,   g_xm);
    cudaGetSymbolAddress((void**)&qkv,  g_qkv);
    cudaGetSymbolAddress((void**)&attn, g_attn);
    cudaGetSymbolAddress((void**)&ffh,  g_ffh);
    cudaGetSymbolAddress((void**)&cpb,  g_cpb);

    // xm = x + spe
    {
        int n4 = MROWS * Dd / 4;
        add_spe_kernel<<<(n4 + 255) / 256, 256>>>(x, spe, xm, n4);
    }

    const dim3 gQKV(768 / 64, MROWS / 128);
    const dim3 gOP (256 / 64, MROWS / 128);
    const dim3 gF1 (1024 / 64, MROWS / 128);
    const dim3 gF2 (256 / 64, MROWS / 128);
    const int lnBlocks = MROWS / 8;

    for (int layer = 0; layer < 2; layer++) {
        int shifted = (layer == 1);

        cpb_kernel<<<WIN2 * WIN2, 256>>>(cw1 + layer * 2 * CPBH, cb1 + layer * CPBH,
                                         cw2 + layer * CPBH * HEADS, cb2 + layer * HEADS, cpb);

        // qkv = (rolled) xm @ qkv_w
        if (shifted)
            sgemm_kernel<0, true ><<<gQKV, 256>>>(xm, qkvw + (size_t)layer * Dd * 768,
                                                  nullptr, qkv, 768, Dd);
        else
            sgemm_kernel<0, false><<<gQKV, 256>>>(xm, qkvw + (size_t)layer * Dd * 768,
                                                  nullptr, qkv, 768, Dd);

        attn_kernel<<<dim3(NW, HEADS, Bb), 256>>>(qkv, tau + layer * HEADS, cpb, attn, shifted);

        // o-proj into ffh (as tmp)
        sgemm_kernel<0, false><<<gOP, 256>>>(attn, ow + (size_t)layer * Dd * Dd,
                                             ob + layer * Dd, ffh, Dd, Dd);

        // xm += LN(oproj), rolled back if shifted
        ln_residual_kernel<<<lnBlocks, 256>>>(ffh, ln1g + layer * Dd, ln1b + layer * Dd,
                                              xm, shifted);

        // ffn1: gelu(xm @ fw1 + fb1) -> ffh
        sgemm_kernel<1, false><<<gF1, 256>>>(xm, fw1 + (size_t)layer * Dd * FF,
                                             fb1 + layer * FF, ffh, FF, Dd);
        // ffn2: ffh @ fw2 + fb2 -> attn (tmp)
        sgemm_kernel<0, false><<<gF2, 256>>>(ffh, fw2 + (size_t)layer * FF * Dd,
                                             fb2 + layer * Dd, attn, Dd, FF);
        // xm += LN(ffn2)
        ln_residual_kernel<<<lnBlocks, 256>>>(attn, ln2g + layer * Dd, ln2b + layer * Dd,
                                              xm, 0);
    }

    ln_final_kernel<<<lnBlocks, 256>>>(xm, ng, nb, out);
}

// round 4
// speedup vs baseline: 1.7651x; 1.7651x over previous
#include <cuda_runtime.h>
#include <cuda_bf16.h>
#include <cstdint>
#include <math.h>

#define Bb     16
#define Hh     56
#define Wd     56
#define Nn     3136
#define Dd     256
#define HEADS  8
#define HD     32
#define WIN    7
#define WIN2   49
#define NWH    8
#define NW     64
#define DISP   3
#define FF     1024
#define CPBH   512
#define EPSLN  1e-5f
#define MROWS  50176   // B * N

// ================= PTX helpers (plain compute_103 features only) =================
__device__ __forceinline__ uint32_t smem_to_u32(const void* p) {
    uint32_t a;
    asm("{ .reg .u64 t; cvta.to.shared.u64 t, %1; cvt.u32.u64 %0, t; }" : "=r"(a) : "l"(p));
    return a;
}
#define CP_ASYNC_CG(dst, src) \
    asm volatile("cp.async.cg.shared.global [%0], [%1], 16;" :: "r"(dst), "l"(src))
#define CP_ASYNC_COMMIT() asm volatile("cp.async.commit_group;" ::: "memory")
#define CP_ASYNC_WAIT(n)  asm volatile("cp.async.wait_group %0;" :: "n"(n) : "memory")

__device__ __forceinline__ void ldsm_x4(uint32_t* r, uint32_t addr) {
    asm volatile("ldmatrix.sync.aligned.m8n8.x4.shared.b16 {%0,%1,%2,%3}, [%4];"
        : "=r"(r[0]), "=r"(r[1]), "=r"(r[2]), "=r"(r[3]) : "r"(addr));
}
__device__ __forceinline__ void mma_bf16(float* c, const uint32_t* a, const uint32_t* b) {
    asm volatile("mma.sync.aligned.m16n8k16.row.col.f32.bf16.bf16.f32 "
        "{%0,%1,%2,%3},{%4,%5,%6,%7},{%8,%9},{%0,%1,%2,%3};"
        : "+f"(c[0]), "+f"(c[1]), "+f"(c[2]), "+f"(c[3])
        : "r"(a[0]), "r"(a[1]), "r"(a[2]), "r"(a[3]), "r"(b[0]), "r"(b[1]));
}

// ================= device scratch =================
__device__ float         g_xm  [MROWS * Dd];
__device__ __nv_bfloat16 g_xmh [MROWS * Dd];
__device__ __nv_bfloat16 g_xml [MROWS * Dd];
__device__ float         g_qkv [MROWS * 3 * Dd];
__device__ __nv_bfloat16 g_ath [MROWS * Dd];
__device__ __nv_bfloat16 g_atl [MROWS * Dd];
__device__ __nv_bfloat16 g_ffh [MROWS * FF];
__device__ __nv_bfloat16 g_ffl [MROWS * FF];
__device__ float         g_tmp [MROWS * Dd];
__device__ float         g_cpb [HEADS * WIN2 * WIN2];
// transposed bf16 weights (hi/lo), per layer:
// [0) qkvT 768x256 | 196608) owT 256x256 | 262144) fw1T 1024x256 | 524288) fw2T 256x1024
#define WLSTRIDE 786432
__device__ __nv_bfloat16 g_wth [2 * WLSTRIDE];
__device__ __nv_bfloat16 g_wtl [2 * WLSTRIDE];

// ================= small helpers =================
__device__ __forceinline__ uint32_t pack_bf2(float a, float b) {
    return (uint32_t)__bfloat16_as_ushort(__float2bfloat16(a)) |
           ((uint32_t)__bfloat16_as_ushort(__float2bfloat16(b)) << 16);
}
__device__ __forceinline__ void split_f4(float4 v, uint2& hi, uint2& lo) {
    __nv_bfloat16 hx = __float2bfloat16(v.x), hy = __float2bfloat16(v.y);
    __nv_bfloat16 hz = __float2bfloat16(v.z), hw = __float2bfloat16(v.w);
    hi.x = (uint32_t)__bfloat16_as_ushort(hx) | ((uint32_t)__bfloat16_as_ushort(hy) << 16);
    hi.y = (uint32_t)__bfloat16_as_ushort(hz) | ((uint32_t)__bfloat16_as_ushort(hw) << 16);
    lo.x = pack_bf2(v.x - __bfloat162float(hx), v.y - __bfloat162float(hy));
    lo.y = pack_bf2(v.z - __bfloat162float(hz), v.w - __bfloat162float(hw));
}

// ================= add SPE =================
__global__ void add_spe_kernel(const float* __restrict__ x, const float* __restrict__ spe,
                               float* __restrict__ xm, __nv_bfloat16* __restrict__ xh,
                               __nv_bfloat16* __restrict__ xl, int n4) {
    int i = blockIdx.x * blockDim.x + threadIdx.x;
    if (i < n4) {
        float4 a = ((const float4*)x)[i];
        float4 b = ((const float4*)spe)[i];
        a.x += b.x; a.y += b.y; a.z += b.z; a.w += b.w;
        ((float4*)xm)[i] = a;
        uint2 h, l; split_f4(a, h, l);
        ((uint2*)xh)[i] = h;
        ((uint2*)xl)[i] = l;
    }
}

// ================= weight transpose + bf16 split: W[K,N] -> T[N,K] =================
__global__ void wtconv_kernel(const float* __restrict__ W, __nv_bfloat16* __restrict__ Th,
                              __nv_bfloat16* __restrict__ Tl, int K, int N) {
    __shared__ float t[32][33];
    int bn = blockIdx.x * 32, bk = blockIdx.y * 32;
    int tx = threadIdx.x, ty = threadIdx.y;
    #pragma unroll
    for (int j = 0; j < 32; j += 8)
        t[ty + j][tx] = W[(size_t)(bk + ty + j) * N + bn + tx];
    __syncthreads();
    #pragma unroll
    for (int j = 0; j < 32; j += 8) {
        float v = t[tx][ty + j];
        __nv_bfloat16 h = __float2bfloat16(v);
        size_t o = (size_t)(bn + ty + j) * K + bk + tx;
        Th[o] = h;
        Tl[o] = __float2bfloat16(v - __bfloat162float(h));
    }
}

// ================= CPB MLP =================
__global__ void cpb_kernel(const float* __restrict__ cw1, const float* __restrict__ cb1,
                           const float* __restrict__ cw2, const float* __restrict__ cb2,
                           float* __restrict__ cpb) {
    int p = blockIdx.x;
    int i = p / WIN2, j = p % WIN2;
    float dy = (float)(j / WIN - i / WIN);
    float dx = (float)(j % WIN - i % WIN);
    float r0 = ((dy > 0.f) - (dy < 0.f)) * log1pf(fabsf(dy));
    float r1 = ((dx > 0.f) - (dx < 0.f)) * log1pf(fabsf(dx));
    int tid = threadIdx.x;
    int c0 = tid, c1 = tid + 256;
    float h0 = fmaxf(r0 * cw1[c0] + r1 * cw1[CPBH + c0] + cb1[c0], 0.f);
    float h1 = fmaxf(r0 * cw1[c1] + r1 * cw1[CPBH + c1] + cb1[c1], 0.f);
    __shared__ float red[256];
    for (int h = 0; h < HEADS; h++) {
        red[tid] = h0 * cw2[c0 * HEADS + h] + h1 * cw2[c1 * HEADS + h];
        __syncthreads();
        for (int s = 128; s > 0; s >>= 1) {
            if (tid < s) red[tid] += red[tid + s];
            __syncthreads();
        }
        if (tid == 0) cpb[h * (WIN2 * WIN2) + p] = red[0] + cb2[h];
        __syncthreads();
    }
}

// ================= HMMA bf16-split GEMM =================
// C[M,Ntot] = (Ah+Al) @ (Bh+Bl)^T, B stored transposed [Ntot,K].
// 128x128 CTA tile, BK=32, 4-stage cp.async pipeline, 8 warps (2x4), 64x32 warp tile.
#define SAS     40                         // padded row stride (elems), 80B
#define TILE_B  (128 * SAS * 2)            // 10240 B per matrix
#define STAGE_B (4 * TILE_B)               // 40960 B per stage
#define STAGES  4
#define GEMM_SMEM (STAGES * STAGE_B)       // 163840 B

template<int ACT, bool GATHER, int OUTMODE>
__global__ void __launch_bounds__(256, 1)
hgemm_kernel(const __nv_bfloat16* __restrict__ Ah, const __nv_bfloat16* __restrict__ Al,
             const __nv_bfloat16* __restrict__ Bth, const __nv_bfloat16* __restrict__ Btl,
             const float* __restrict__ bias, float* __restrict__ Cf,
             __nv_bfloat16* __restrict__ Ch, __nv_bfloat16* __restrict__ Cl,
             int Ntot, int K) {
    extern __shared__ char smem_raw[];
    const uint32_t sbase = smem_to_u32(smem_raw);
    const int tid  = threadIdx.x;
    const int lane = tid & 31, wid = tid >> 5;
    const int warpM = wid >> 2, warpN = wid & 3;
    const int bm = blockIdx.y * 128, bn = blockIdx.x * 128;

    // ---- per-thread cp.async source pointers (2 chunks per matrix) ----
    const __nv_bfloat16 *pAh[2], *pAl[2], *pBh[2], *pBl[2];
    uint32_t soff[2];
    #pragma unroll
    for (int l = 0; l < 2; l++) {
        int c = tid + l * 256;              // 512 chunks: 128 rows x 4 (16B each)
        int r = c >> 2, q = c & 3;
        int gm = bm + r;
        if (GATHER) {
            int b = gm / Nn, rem = gm - b * Nn;
            int h = rem / Wd, w = rem - h * Wd;
            h = (h + DISP) % Hh; w = (w + DISP) % Wd;
            gm = b * Nn + h * Wd + w;
        }
        pAh[l] = Ah + (size_t)gm * K + q * 8;
        pAl[l] = Al + (size_t)gm * K + q * 8;
        int n = bn + r;
        pBh[l] = Bth + (size_t)n * K + q * 8;
        pBl[l] = Btl + (size_t)n * K + q * 8;
        soff[l] = (uint32_t)(r * (SAS * 2) + q * 16);
    }

    float acc[4][4][4];
    #pragma unroll
    for (int m = 0; m < 4; m++)
        #pragma unroll
        for (int n = 0; n < 4; n++)
            #pragma unroll
            for (int e = 0; e < 4; e++) acc[m][n][e] = 0.f;

    const int nch = K >> 5;

    // ---- loaders ----
    auto load_stage = [&](int c) {
        uint32_t stg = sbase + (uint32_t)(c & (STAGES - 1)) * STAGE_B;
        int kt = c << 5;
        #pragma unroll
        for (int l = 0; l < 2; l++) {
            CP_ASYNC_CG(stg + soff[l],                 pAh[l] + kt);
            CP_ASYNC_CG(stg + TILE_B + soff[l],        pAl[l] + kt);
            CP_ASYNC_CG(stg + 2 * TILE_B + soff[l],    pBh[l] + kt);
            CP_ASYNC_CG(stg + 3 * TILE_B + soff[l],    pBl[l] + kt);
        }
    };

    // ---- ldmatrix address components ----
    const int arow = (lane & 15);           // A: lanes 0-15 rows, 16-31 k+8
    const int ahalf = (lane >> 4);
    const int bidx = lane & 7;              // B x4: idx within 8
    const int bkh  = (lane >> 3) & 1;       // k half
    const int bsub = lane >> 4;             // n sub-tile (0/1)

    // prologue
    #pragma unroll
    for (int s = 0; s < STAGES - 1; s++) {
        if (s < nch) load_stage(s);
        CP_ASYNC_COMMIT();
    }

    for (int c = 0; c < nch; c++) {
        CP_ASYNC_WAIT(STAGES - 2);
        __syncthreads();
        if (c + STAGES - 1 < nch) load_stage(c + STAGES - 1);
        CP_ASYNC_COMMIT();

        uint32_t stg = sbase + (uint32_t)(c & (STAGES - 1)) * STAGE_B;
        #pragma unroll
        for (int ks = 0; ks < 2; ks++) {
            uint32_t ah[4][4], al[4][4], bh[4][2], bl[4][2];
            #pragma unroll
            for (int m = 0; m < 4; m++) {
                uint32_t off = (uint32_t)((warpM * 64 + m * 16 + arow) * (SAS * 2)
                                          + (ks * 16 + ahalf * 8) * 2);
                ldsm_x4(ah[m], stg + off);
                ldsm_x4(al[m], stg + TILE_B + off);
            }
            #pragma unroll
            for (int pr = 0; pr < 2; pr++) {
                uint32_t off = (uint32_t)((warpN * 32 + pr * 16 + bsub * 8 + bidx) * (SAS * 2)
                                          + (ks * 16 + bkh * 8) * 2);
                uint32_t t[4];
                ldsm_x4(t, stg + 2 * TILE_B + off);
                bh[pr * 2][0] = t[0]; bh[pr * 2][1] = t[1];
                bh[pr * 2 + 1][0] = t[2]; bh[pr * 2 + 1][1] = t[3];
                ldsm_x4(t, stg + 3 * TILE_B + off);
                bl[pr * 2][0] = t[0]; bl[pr * 2][1] = t[1];
                bl[pr * 2 + 1][0] = t[2]; bl[pr * 2 + 1][1] = t[3];
            }
            #pragma unroll
            for (int m = 0; m < 4; m++)
                #pragma unroll
                for (int n = 0; n < 4; n++) mma_bf16(acc[m][n], ah[m], bh[n]);
            #pragma unroll
            for (int m = 0; m < 4; m++)
                #pragma unroll
                for (int n = 0; n < 4; n++) mma_bf16(acc[m][n], ah[m], bl[n]);
            #pragma unroll
            for (int m = 0; m < 4; m++)
                #pragma unroll
                for (int n = 0; n < 4; n++) mma_bf16(acc[m][n], al[m], bh[n]);
        }
    }

    // ---- epilogue ----
    const int g = lane >> 2, q = lane & 3;
    #pragma unroll
    for (int m = 0; m < 4; m++) {
        #pragma unroll
        for (int n = 0; n < 4; n++) {
            int col = bn + warpN * 32 + n * 8 + 2 * q;
            float b0 = bias ? bias[col] : 0.f;
            float b1 = bias ? bias[col + 1] : 0.f;
            #pragma unroll
            for (int hrow = 0; hrow < 2; hrow++) {
                int row = bm + warpM * 64 + m * 16 + g + hrow * 8;
                float v0 = acc[m][n][hrow * 2 + 0] + b0;
                float v1 = acc[m][n][hrow * 2 + 1] + b1;
                if (ACT == 1) {
                    v0 = v0 * 0.5f * (1.f + erff(v0 * 0.7071067811865476f));
                    v1 = v1 * 0.5f * (1.f + erff(v1 * 0.7071067811865476f));
                }
                if (OUTMODE == 0) {
                    *(float2*)(Cf + (size_t)row * Ntot + col) = make_float2(v0, v1);
                } else {
                    __nv_bfloat16 h0 = __float2bfloat16(v0);
                    __nv_bfloat16 h1 = __float2bfloat16(v1);
                    *(uint32_t*)(Ch + (size_t)row * Ntot + col) =
                        (uint32_t)__bfloat16_as_ushort(h0) |
                        ((uint32_t)__bfloat16_as_ushort(h1) << 16);
                    *(uint32_t*)(Cl + (size_t)row * Ntot + col) =
                        pack_bf2(v0 - __bfloat162float(h0), v1 - __bfloat162float(h1));
                }
            }
        }
    }
}

// ================= window attention (emits bf16 hi/lo) =================
__global__ void __launch_bounds__(256)
attn_kernel(const float* __restrict__ qkv, const float* __restrict__ tau,
            const float* __restrict__ cpb, __nv_bfloat16* __restrict__ outh,
            __nv_bfloat16* __restrict__ outl, int shifted) {
    __shared__ float sq[64 * 33];
    __shared__ float sk[64 * 33];
    __shared__ float sv[49 * 33];
    __shared__ float sd[64 * 52];

    const int wi   = blockIdx.x;
    const int head = blockIdx.y;
    const int b    = blockIdx.z;
    const int wh = wi >> 3, ww = wi & 7;
    const int tid = threadIdx.x;

    for (int e = tid; e < 64 * 32; e += 256) {
        int r = e >> 5, d = e & 31;
        if (r < WIN2) {
            int i = r / WIN, j = r % WIN;
            int m = b * Nn + (wh * WIN + i) * Wd + (ww * WIN + j);
            const float* base = qkv + (size_t)m * 768 + head * HD + d;
            sq[r * 33 + d] = base[0];
            sk[r * 33 + d] = base[256];
            sv[r * 33 + d] = base[512];
        } else {
            sq[r * 33 + d] = 0.f;
            sk[r * 33 + d] = 0.f;
        }
    }
    __syncthreads();

    for (int t = tid; t < 2 * WIN2; t += 256) {
        float* row = (t < WIN2) ? (sq + t * 33) : (sk + (t - WIN2) * 33);
        float s = 0.f;
        #pragma unroll
        for (int d = 0; d < HD; d++) s += row[d] * row[d];
        float inv = 1.f / fmaxf(sqrtf(s), 1e-12f);
        #pragma unroll
        for (int d = 0; d < HD; d++) row[d] *= inv;
    }
    __syncthreads();

    const float tscale = 1.f / fmaxf(tau[head], 0.01f);
    const int tx = tid & 15, ty = tid >> 4;

    float acc[4][4];
    #pragma unroll
    for (int u = 0; u < 4; u++)
        #pragma unroll
        for (int v = 0; v < 4; v++) acc[u][v] = 0.f;
    #pragma unroll
    for (int kk = 0; kk < HD; kk++) {
        float a[4], bb[4];
        #pragma unroll
        for (int u = 0; u < 4; u++) a[u]  = sq[(ty + u * 16) * 33 + kk];
        #pragma unroll
        for (int v = 0; v < 4; v++) bb[v] = sk[(tx + v * 16) * 33 + kk];
        #pragma unroll
        for (int u = 0; u < 4; u++)
            #pragma unroll
            for (int v = 0; v < 4; v++) acc[u][v] += a[u] * bb[v];
    }
    #pragma unroll
    for (int u = 0; u < 4; u++) {
        int i = ty + u * 16;
        if (i >= WIN2) continue;
        #pragma unroll
        for (int v = 0; v < 4; v++) {
            int j = tx + v * 16;
            if (j >= WIN2) continue;
            float val = acc[u][v] * tscale + cpb[head * (WIN2 * WIN2) + i * WIN2 + j];
            if (shifted) {
                if (wh == NWH - 1 && ((i >= 28) != (j >= 28))) val = -1e30f;
                if (ww == NWH - 1 && (((i % WIN) >= 4) != ((j % WIN) >= 4))) val = -1e30f;
            }
            sd[i * 52 + j] = val;
        }
    }
    __syncthreads();

    const int lane = tid & 31, wrp = tid >> 5;
    for (int r = wrp; r < WIN2; r += 8) {
        float v0 = sd[r * 52 + lane];
        float v1 = (lane + 32 < WIN2) ? sd[r * 52 + lane + 32] : -3e38f;
        float mx = fmaxf(v0, v1);
        #pragma unroll
        for (int o = 16; o > 0; o >>= 1) mx = fmaxf(mx, __shfl_xor_sync(~0u, mx, o));
        float e0 = __expf(v0 - mx);
        float e1 = (lane + 32 < WIN2) ? __expf(v1 - mx) : 0.f;
        float s = e0 + e1;
        #pragma unroll
        for (int o = 16; o > 0; o >>= 1) s += __shfl_xor_sync(~0u, s, o);
        float inv = 1.f / s;
        sd[r * 52 + lane] = e0 * inv;
        if (lane + 32 < WIN2) sd[r * 52 + lane + 32] = e1 * inv;
    }
    __syncthreads();

    float o2[4][2];
    #pragma unroll
    for (int u = 0; u < 4; u++) { o2[u][0] = 0.f; o2[u][1] = 0.f; }
    for (int j = 0; j < WIN2; j++) {
        float p[4];
        #pragma unroll
        for (int u = 0; u < 4; u++) p[u] = sd[(ty + u * 16) * 52 + j];
        float v0 = sv[j * 33 + tx * 2];
        float v1 = sv[j * 33 + tx * 2 + 1];
        #pragma unroll
        for (int u = 0; u < 4; u++) {
            o2[u][0] += p[u] * v0;
            o2[u][1] += p[u] * v1;
        }
    }
    #pragma unroll
    for (int u = 0; u < 4; u++) {
        int i = ty + u * 16;
        if (i < WIN2) {
            int ii = i / WIN, jj = i % WIN;
            int m = b * Nn + (wh * WIN + ii) * Wd + (ww * WIN + jj);
            size_t off = (size_t)m * Dd + head * HD + tx * 2;
            __nv_bfloat16 h0 = __float2bfloat16(o2[u][0]);
            __nv_bfloat16 h1 = __float2bfloat16(o2[u][1]);
            *(uint32_t*)(outh + off) = (uint32_t)__bfloat16_as_ushort(h0) |
                                       ((uint32_t)__bfloat16_as_ushort(h1) << 16);
            *(uint32_t*)(outl + off) = pack_bf2(o2[u][0] - __bfloat162float(h0),
                                                o2[u][1] - __bfloat162float(h1));
        }
    }
}

// ================= LN + residual =================
__global__ void ln_residual_kernel(const float* __restrict__ A, const float* __restrict__ g,
                                   const float* __restrict__ be, float* __restrict__ xm,
                                   __nv_bfloat16* __restrict__ xh, __nv_bfloat16* __restrict__ xl,
                                   int gather) {
    int row = blockIdx.x * 8 + (threadIdx.x >> 5);
    int lane = threadIdx.x & 31;
    int src = row;
    if (gather) {
        int b = row / Nn, rem = row % Nn;
        int h = rem / Wd, w = rem % Wd;
        src = b * Nn + ((h + Hh - DISP) % Hh) * Wd + ((w + Wd - DISP) % Wd);
    }
    const float4* a4 = (const float4*)(A + (size_t)src * Dd);
    float4 v0 = a4[lane], v1 = a4[lane + 32];
    float s  = v0.x + v0.y + v0.z + v0.w + v1.x + v1.y + v1.z + v1.w;
    float s2 = v0.x*v0.x + v0.y*v0.y + v0.z*v0.z + v0.w*v0.w
             + v1.x*v1.x + v1.y*v1.y + v1.z*v1.z + v1.w*v1.w;
    #pragma unroll
    for (int o = 16; o > 0; o >>= 1) {
        s  += __shfl_xor_sync(~0u, s, o);
        s2 += __shfl_xor_sync(~0u, s2, o);
    }
    float mean = s * (1.f / Dd);
    float var  = s2 * (1.f / Dd) - mean * mean;
    float inv  = rsqrtf(var + EPSLN);

    float4 g0 = ((const float4*)g)[lane],  g1 = ((const float4*)g)[lane + 32];
    float4 b0 = ((const float4*)be)[lane], b1 = ((const float4*)be)[lane + 32];
    float4* x4 = (float4*)(xm + (size_t)row * Dd);
    float4 r0 = x4[lane], r1 = x4[lane + 32];
    r0.x += (v0.x - mean) * inv * g0.x + b0.x;
    r0.y += (v0.y - mean) * inv * g0.y + b0.y;
    r0.z += (v0.z - mean) * inv * g0.z + b0.z;
    r0.w += (v0.w - mean) * inv * g0.w + b0.w;
    r1.x += (v1.x - mean) * inv * g1.x + b1.x;
    r1.y += (v1.y - mean) * inv * g1.y + b1.y;
    r1.z += (v1.z - mean) * inv * g1.z + b1.z;
    r1.w += (v1.w - mean) * inv * g1.w + b1.w;
    x4[lane] = r0; x4[lane + 32] = r1;

    uint2 h, l;
    size_t e0 = (size_t)row * Dd + lane * 4;
    size_t e1 = e0 + 128;
    split_f4(r0, h, l);
    *(uint2*)(xh + e0) = h; *(uint2*)(xl + e0) = l;
    split_f4(r1, h, l);
    *(uint2*)(xh + e1) = h; *(uint2*)(xl + e1) = l;
}

// ================= final LN =================
__global__ void ln_final_kernel(const float* __restrict__ A, const float* __restrict__ g,
                                const float* __restrict__ be, float* __restrict__ out) {
    int row = blockIdx.x * 8 + (threadIdx.x >> 5);
    int lane = threadIdx.x & 31;
    const float4* a4 = (const float4*)(A + (size_t)row * Dd);
    float4 v0 = a4[lane], v1 = a4[lane + 32];
    float s  = v0.x + v0.y + v0.z + v0.w + v1.x + v1.y + v1.z + v1.w;
    float s2 = v0.x*v0.x + v0.y*v0.y + v0.z*v0.z + v0.w*v0.w
             + v1.x*v1.x + v1.y*v1.y + v1.z*v1.z + v1.w*v1.w;
    #pragma unroll
    for (int o = 16; o > 0; o >>= 1) {
        s  += __shfl_xor_sync(~0u, s, o);
        s2 += __shfl_xor_sync(~0u, s2, o);
    }
    float mean = s * (1.f / Dd);
    float var  = s2 * (1.f / Dd) - mean * mean;
    float inv  = rsqrtf(var + EPSLN);
    float4 g0 = ((const float4*)g)[lane],  g1 = ((const float4*)g)[lane + 32];
    float4 b0 = ((const float4*)be)[lane], b1 = ((const float4*)be)[lane + 32];
    float4 o0, o1;
    o0.x = (v0.x - mean) * inv * g0.x + b0.x;
    o0.y = (v0.y - mean) * inv * g0.y + b0.y;
    o0.z = (v0.z - mean) * inv * g0.z + b0.z;
    o0.w = (v0.w - mean) * inv * g0.w + b0.w;
    o1.x = (v1.x - mean) * inv * g1.x + b1.x;
    o1.y = (v1.y - mean) * inv * g1.y + b1.y;
    o1.z = (v1.z - mean) * inv * g1.z + b1.z;
    o1.w = (v1.w - mean) * inv * g1.w + b1.w;
    float4* out4 = (float4*)(out + (size_t)row * Dd);
    out4[lane] = o0; out4[lane + 32] = o1;
}

// ================= launch =================
extern "C" void kernel_launch(void* const* d_in, const int* in_sizes, int n_in,
                              void* d_out, int out_size) {
    const float* x    = (const float*)d_in[0];
    const float* spe  = (const float*)d_in[1];
    const float* qkvw = (const float*)d_in[2];
    const float* tau  = (const float*)d_in[3];
    const float* cw1  = (const float*)d_in[4];
    const float* cb1  = (const float*)d_in[5];
    const float* cw2  = (const float*)d_in[6];
    const float* cb2  = (const float*)d_in[7];
    const float* ow   = (const float*)d_in[8];
    const float* ob   = (const float*)d_in[9];
    const float* ln1g = (const float*)d_in[10];
    const float* ln1b = (const float*)d_in[11];
    const float* fw1  = (const float*)d_in[12];
    const float* fb1  = (const float*)d_in[13];
    const float* fw2  = (const float*)d_in[14];
    const float* fb2  = (const float*)d_in[15];
    const float* ln2g = (const float*)d_in[16];
    const float* ln2b = (const float*)d_in[17];
    const float* ng   = (const float*)d_in[18];
    const float* nb   = (const float*)d_in[19];
    float* out = (float*)d_out;

    float *xm, *qkv, *tmp, *cpb;
    __nv_bfloat16 *xmh, *xml, *ath, *atl, *ffh, *ffl, *wth, *wtl;
    cudaGetSymbolAddress((void**)&xm,  g_xm);
    cudaGetSymbolAddress((void**)&qkv, g_qkv);
    cudaGetSymbolAddress((void**)&tmp, g_tmp);
    cudaGetSymbolAddress((void**)&cpb, g_cpb);
    cudaGetSymbolAddress((void**)&xmh, g_xmh);
    cudaGetSymbolAddress((void**)&xml, g_xml);
    cudaGetSymbolAddress((void**)&ath, g_ath);
    cudaGetSymbolAddress((void**)&atl, g_atl);
    cudaGetSymbolAddress((void**)&ffh, g_ffh);
    cudaGetSymbolAddress((void**)&ffl, g_ffl);
    cudaGetSymbolAddress((void**)&wth, g_wth);
    cudaGetSymbolAddress((void**)&wtl, g_wtl);

    cudaFuncSetAttribute(hgemm_kernel<0, false, 0>, cudaFuncAttributeMaxDynamicSharedMemorySize, GEMM_SMEM);
    cudaFuncSetAttribute(hgemm_kernel<0, true,  0>, cudaFuncAttributeMaxDynamicSharedMemorySize, GEMM_SMEM);
    cudaFuncSetAttribute(hgemm_kernel<1, false, 1>, cudaFuncAttributeMaxDynamicSharedMemorySize, GEMM_SMEM);

    // weight transpose + bf16 split (both layers)
    for (int l = 0; l < 2; l++) {
        size_t wo = (size_t)l * WLSTRIDE;
        wtconv_kernel<<<dim3(768 / 32, 256 / 32), dim3(32, 8)>>>(
            qkvw + (size_t)l * Dd * 768, wth + wo, wtl + wo, 256, 768);
        wtconv_kernel<<<dim3(256 / 32, 256 / 32), dim3(32, 8)>>>(
            ow + (size_t)l * Dd * Dd, wth + wo + 196608, wtl + wo + 196608, 256, 256);
        wtconv_kernel<<<dim3(1024 / 32, 256 / 32), dim3(32, 8)>>>(
            fw1 + (size_t)l * Dd * FF, wth + wo + 262144, wtl + wo + 262144, 256, 1024);
        wtconv_kernel<<<dim3(256 / 32, 1024 / 32), dim3(32, 8)>>>(
            fw2 + (size_t)l * FF * Dd, wth + wo + 524288, wtl + wo + 524288, 1024, 256);
    }

    // xm = x + spe (+ bf16 split)
    {
        int n4 = MROWS * Dd / 4;
        add_spe_kernel<<<(n4 + 255) / 256, 256>>>(x, spe, xm, xmh, xml, n4);
    }

    const int lnBlocks = MROWS / 8;
    for (int layer = 0; layer < 2; layer++) {
        int shifted = (layer == 1);
        size_t wo = (size_t)layer * WLSTRIDE;

        cpb_kernel<<<WIN2 * WIN2, 256>>>(cw1 + layer * 2 * CPBH, cb1 + layer * CPBH,
                                         cw2 + layer * CPBH * HEADS, cb2 + layer * HEADS, cpb);

        // qkv = (rolled) xm @ qkv_w -> fp32
        if (shifted)
            hgemm_kernel<0, true, 0><<<dim3(6, 392), 256, GEMM_SMEM>>>(
                xmh, xml, wth + wo, wtl + wo, nullptr, qkv, nullptr, nullptr, 768, 256);
        else
            hgemm_kernel<0, false, 0><<<dim3(6, 392), 256, GEMM_SMEM>>>(
                xmh, xml, wth + wo, wtl + wo, nullptr, qkv, nullptr, nullptr, 768, 256);

        attn_kernel<<<dim3(NW, HEADS, Bb), 256>>>(qkv, tau + layer * HEADS, cpb, ath, atl, shifted);

        // o-proj -> tmp (fp32)
        hgemm_kernel<0, false, 0><<<dim3(2, 392), 256, GEMM_SMEM>>>(
            ath, atl, wth + wo + 196608, wtl + wo + 196608, ob + layer * Dd,
            tmp, nullptr, nullptr, 256, 256);

        // xm += LN(oproj) (rolled back if shifted)
        ln_residual_kernel<<<lnBlocks, 256>>>(tmp, ln1g + layer * Dd, ln1b + layer * Dd,
                                              xm, xmh, xml, shifted);

        // ffn1: gelu(xm @ fw1 + fb1) -> bf16 hi/lo
        hgemm_kernel<1, false, 1><<<dim3(8, 392), 256, GEMM_SMEM>>>(
            xmh, xml, wth + wo + 262144, wtl + wo + 262144, fb1 + layer * FF,
            nullptr, ffh, ffl, 1024, 256);

        // ffn2 -> tmp (fp32)
        hgemm_kernel<0, false, 0><<<dim3(2, 392), 256, GEMM_SMEM>>>(
            ffh, ffl, wth + wo + 524288, wtl + wo + 524288, fb2 + layer * Dd,
            tmp, nullptr, nullptr, 256, 1024);

        // xm += LN(ffn2)
        ln_residual_kernel<<<lnBlocks, 256>>>(tmp, ln2g + layer * Dd, ln2b + layer * Dd,
                                              xm, xmh, xml, 0);
    }

    ln_final_kernel<<<lnBlocks, 256>>>(xm, ng, nb, out);
}

// round 5
// speedup vs baseline: 1.8727x; 1.0610x over previous
#include <cuda_runtime.h>
#include <cuda_bf16.h>
#include <cstdint>
#include <math.h>

#define Bb     16
#define Hh     56
#define Wd     56
#define Nn     3136
#define Dd     256
#define HEADS  8
#define HD     32
#define WIN    7
#define WIN2   49
#define NWH    8
#define NW     64
#define DISP   3
#define FF     1024
#define CPBH   512
#define EPSLN  1e-5f
#define MROWS  50176   // B * N

// ================= PTX helpers (plain compute_103 features only) =================
__device__ __forceinline__ uint32_t smem_to_u32(const void* p) {
    uint32_t a;
    asm("{ .reg .u64 t; cvta.to.shared.u64 t, %1; cvt.u32.u64 %0, t; }" : "=r"(a) : "l"(p));
    return a;
}
#define CP_ASYNC_CG(dst, src) \
    asm volatile("cp.async.cg.shared.global [%0], [%1], 16;" :: "r"(dst), "l"(src))
#define CP_ASYNC_COMMIT() asm volatile("cp.async.commit_group;" ::: "memory")
#define CP_ASYNC_WAIT(n)  asm volatile("cp.async.wait_group %0;" :: "n"(n) : "memory")

__device__ __forceinline__ void ldsm_x4(uint32_t* r, uint32_t addr) {
    asm volatile("ldmatrix.sync.aligned.m8n8.x4.shared.b16 {%0,%1,%2,%3}, [%4];"
        : "=r"(r[0]), "=r"(r[1]), "=r"(r[2]), "=r"(r[3]) : "r"(addr));
}
__device__ __forceinline__ void mma_bf16(float* c, const uint32_t* a, const uint32_t* b) {
    asm volatile("mma.sync.aligned.m16n8k16.row.col.f32.bf16.bf16.f32 "
        "{%0,%1,%2,%3},{%4,%5,%6,%7},{%8,%9},{%0,%1,%2,%3};"
        : "+f"(c[0]), "+f"(c[1]), "+f"(c[2]), "+f"(c[3])
        : "r"(a[0]), "r"(a[1]), "r"(a[2]), "r"(a[3]), "r"(b[0]), "r"(b[1]));
}

// ================= device scratch =================
__device__ float         g_xm  [MROWS * Dd];
__device__ __nv_bfloat16 g_xmh [MROWS * Dd];
__device__ __nv_bfloat16 g_xml [MROWS * Dd];
__device__ float         g_qkv [MROWS * 3 * Dd];
__device__ __nv_bfloat16 g_ath [MROWS * Dd];
__device__ __nv_bfloat16 g_atl [MROWS * Dd];
__device__ __nv_bfloat16 g_ffh [MROWS * FF];
__device__ __nv_bfloat16 g_ffl [MROWS * FF];
__device__ float         g_tmp [MROWS * Dd];
__device__ float         g_cpb [HEADS * WIN2 * WIN2];
// transposed bf16 weights (hi/lo), per layer:
// [0) qkvT 768x256 | 196608) owT 256x256 | 262144) fw1T 1024x256 | 524288) fw2T 256x1024
#define WLSTRIDE 786432
__device__ __nv_bfloat16 g_wth [2 * WLSTRIDE];
__device__ __nv_bfloat16 g_wtl [2 * WLSTRIDE];

// ================= small helpers =================
__device__ __forceinline__ uint32_t pack_bf2(float a, float b) {
    return (uint32_t)__bfloat16_as_ushort(__float2bfloat16(a)) |
           ((uint32_t)__bfloat16_as_ushort(__float2bfloat16(b)) << 16);
}
__device__ __forceinline__ void split_f4(float4 v, uint2& hi, uint2& lo) {
    __nv_bfloat16 hx = __float2bfloat16(v.x), hy = __float2bfloat16(v.y);
    __nv_bfloat16 hz = __float2bfloat16(v.z), hw = __float2bfloat16(v.w);
    hi.x = (uint32_t)__bfloat16_as_ushort(hx) | ((uint32_t)__bfloat16_as_ushort(hy) << 16);
    hi.y = (uint32_t)__bfloat16_as_ushort(hz) | ((uint32_t)__bfloat16_as_ushort(hw) << 16);
    lo.x = pack_bf2(v.x - __bfloat162float(hx), v.y - __bfloat162float(hy));
    lo.y = pack_bf2(v.z - __bfloat162float(hz), v.w - __bfloat162float(hw));
}

// ================= add SPE =================
__global__ void add_spe_kernel(const float* __restrict__ x, const float* __restrict__ spe,
                               float* __restrict__ xm, __nv_bfloat16* __restrict__ xh,
                               __nv_bfloat16* __restrict__ xl, int n4) {
    int i = blockIdx.x * blockDim.x + threadIdx.x;
    if (i < n4) {
        float4 a = ((const float4*)x)[i];
        float4 b = ((const float4*)spe)[i];
        a.x += b.x; a.y += b.y; a.z += b.z; a.w += b.w;
        ((float4*)xm)[i] = a;
        uint2 h, l; split_f4(a, h, l);
        ((uint2*)xh)[i] = h;
        ((uint2*)xl)[i] = l;
    }
}

// ================= weight transpose + bf16 split: W[K,N] -> T[N,K] =================
__global__ void wtconv_kernel(const float* __restrict__ W, __nv_bfloat16* __restrict__ Th,
                              __nv_bfloat16* __restrict__ Tl, int K, int N) {
    __shared__ float t[32][33];
    int bn = blockIdx.x * 32, bk = blockIdx.y * 32;
    int tx = threadIdx.x, ty = threadIdx.y;
    #pragma unroll
    for (int j = 0; j < 32; j += 8)
        t[ty + j][tx] = W[(size_t)(bk + ty + j) * N + bn + tx];
    __syncthreads();
    #pragma unroll
    for (int j = 0; j < 32; j += 8) {
        float v = t[tx][ty + j];
        __nv_bfloat16 h = __float2bfloat16(v);
        size_t o = (size_t)(bn + ty + j) * K + bk + tx;
        Th[o] = h;
        Tl[o] = __float2bfloat16(v - __bfloat162float(h));
    }
}

// ================= CPB MLP =================
__global__ void cpb_kernel(const float* __restrict__ cw1, const float* __restrict__ cb1,
                           const float* __restrict__ cw2, const float* __restrict__ cb2,
                           float* __restrict__ cpb) {
    int p = blockIdx.x;
    int i = p / WIN2, j = p % WIN2;
    float dy = (float)(j / WIN - i / WIN);
    float dx = (float)(j % WIN - i % WIN);
    float r0 = ((dy > 0.f) - (dy < 0.f)) * log1pf(fabsf(dy));
    float r1 = ((dx > 0.f) - (dx < 0.f)) * log1pf(fabsf(dx));
    int tid = threadIdx.x;
    int c0 = tid, c1 = tid + 256;
    float h0 = fmaxf(r0 * cw1[c0] + r1 * cw1[CPBH + c0] + cb1[c0], 0.f);
    float h1 = fmaxf(r0 * cw1[c1] + r1 * cw1[CPBH + c1] + cb1[c1], 0.f);
    __shared__ float red[256];
    for (int h = 0; h < HEADS; h++) {
        red[tid] = h0 * cw2[c0 * HEADS + h] + h1 * cw2[c1 * HEADS + h];
        __syncthreads();
        for (int s = 128; s > 0; s >>= 1) {
            if (tid < s) red[tid] += red[tid + s];
            __syncthreads();
        }
        if (tid == 0) cpb[h * (WIN2 * WIN2) + p] = red[0] + cb2[h];
        __syncthreads();
    }
}

// ================= HMMA bf16-split GEMM =================
// C[M,Ntot] = (Ah+Al) @ (Bh+Bl)^T, B stored transposed [Ntot,K].
// 256x128 CTA tile, BK=32, 3-stage cp.async pipeline, 8 warps (4x2), 64x64 warp tile.
#define SAS      40                         // padded row stride (elems), 80B
#define AH_OFF   0
#define AL_OFF   20480                      // 256*80
#define BH_OFF   40960
#define BL_OFF   51200                      // +128*80
#define STAGE_B  61440
#define STAGES   3
#define GEMM_SMEM (STAGES * STAGE_B)        // 184320 B

template<int ACT, bool GATHER, int OUTMODE>
__global__ void __launch_bounds__(256, 1)
hgemm_kernel(const __nv_bfloat16* __restrict__ Ah, const __nv_bfloat16* __restrict__ Al,
             const __nv_bfloat16* __restrict__ Bth, const __nv_bfloat16* __restrict__ Btl,
             const float* __restrict__ bias, float* __restrict__ Cf,
             __nv_bfloat16* __restrict__ Ch, __nv_bfloat16* __restrict__ Cl,
             int Ntot, int K) {
    extern __shared__ char smem_raw[];
    const uint32_t sbase = smem_to_u32(smem_raw);
    const int tid  = threadIdx.x;
    const int lane = tid & 31, wid = tid >> 5;
    const int warpM = wid >> 1, warpN = wid & 1;   // 4x2
    const int bm = blockIdx.y * 256, bn = blockIdx.x * 128;

    // ---- per-thread cp.async source pointers ----
    // A: 256 rows x 4 chunks = 1024 chunks -> 4 per thread (hi & lo share row/offset)
    // B: 128 rows x 4 chunks = 512 chunks  -> 2 per thread
    const __nv_bfloat16 *pAh[4], *pAl[4], *pBh[2], *pBl[2];
    uint32_t aoff[4], boff[2];
    #pragma unroll
    for (int l = 0; l < 4; l++) {
        int c = tid + l * 256;
        int r = c >> 2, q = c & 3;
        int gm = bm + r;
        if (GATHER) {
            int b = gm / Nn, rem = gm - b * Nn;
            int h = rem / Wd, w = rem - h * Wd;
            h = (h + DISP) % Hh; w = (w + DISP) % Wd;
            gm = b * Nn + h * Wd + w;
        }
        pAh[l] = Ah + (size_t)gm * K + q * 8;
        pAl[l] = Al + (size_t)gm * K + q * 8;
        aoff[l] = (uint32_t)(r * (SAS * 2) + q * 16);
    }
    #pragma unroll
    for (int l = 0; l < 2; l++) {
        int c = tid + l * 256;
        int r = c >> 2, q = c & 3;
        pBh[l] = Bth + (size_t)(bn + r) * K + q * 8;
        pBl[l] = Btl + (size_t)(bn + r) * K + q * 8;
        boff[l] = (uint32_t)(r * (SAS * 2) + q * 16);
    }

    float acc[4][8][4];
    #pragma unroll
    for (int m = 0; m < 4; m++)
        #pragma unroll
        for (int n = 0; n < 8; n++)
            #pragma unroll
            for (int e = 0; e < 4; e++) acc[m][n][e] = 0.f;

    const int nch = K >> 5;

    auto load_stage = [&](int c, int sc) {
        uint32_t stg = sbase + (uint32_t)sc * STAGE_B;
        int kt = c << 5;
        #pragma unroll
        for (int l = 0; l < 4; l++) {
            CP_ASYNC_CG(stg + AH_OFF + aoff[l], pAh[l] + kt);
            CP_ASYNC_CG(stg + AL_OFF + aoff[l], pAl[l] + kt);
        }
        #pragma unroll
        for (int l = 0; l < 2; l++) {
            CP_ASYNC_CG(stg + BH_OFF + boff[l], pBh[l] + kt);
            CP_ASYNC_CG(stg + BL_OFF + boff[l], pBl[l] + kt);
        }
    };

    // ---- ldmatrix address components ----
    const int arow  = (lane & 15);
    const int ahalf = (lane >> 4);
    const int bidx  = lane & 7;
    const int bkh   = (lane >> 3) & 1;
    const int bsub  = lane >> 4;

    // prologue: fill stages 0,1
    load_stage(0, 0);
    CP_ASYNC_COMMIT();
    if (nch > 1) load_stage(1, 1);
    CP_ASYNC_COMMIT();

    int sc = 0, scn = 2;
    for (int c = 0; c < nch; c++) {
        CP_ASYNC_WAIT(1);
        __syncthreads();
        if (c + 2 < nch) load_stage(c + 2, scn);
        CP_ASYNC_COMMIT();

        uint32_t stg = sbase + (uint32_t)sc * STAGE_B;
        #pragma unroll
        for (int ks = 0; ks < 2; ks++) {
            uint32_t ah[4][4], al[4][4], bh[8][2], bl[8][2];
            #pragma unroll
            for (int m = 0; m < 4; m++) {
                uint32_t off = (uint32_t)((warpM * 64 + m * 16 + arow) * (SAS * 2)
                                          + (ks * 16 + ahalf * 8) * 2);
                ldsm_x4(ah[m], stg + AH_OFF + off);
                ldsm_x4(al[m], stg + AL_OFF + off);
            }
            #pragma unroll
            for (int pr = 0; pr < 4; pr++) {
                uint32_t off = (uint32_t)((warpN * 64 + pr * 16 + bsub * 8 + bidx) * (SAS * 2)
                                          + (ks * 16 + bkh * 8) * 2);
                uint32_t t[4];
                ldsm_x4(t, stg + BH_OFF + off);
                bh[pr * 2][0] = t[0]; bh[pr * 2][1] = t[1];
                bh[pr * 2 + 1][0] = t[2]; bh[pr * 2 + 1][1] = t[3];
                ldsm_x4(t, stg + BL_OFF + off);
                bl[pr * 2][0] = t[0]; bl[pr * 2][1] = t[1];
                bl[pr * 2 + 1][0] = t[2]; bl[pr * 2 + 1][1] = t[3];
            }
            #pragma unroll
            for (int m = 0; m < 4; m++)
                #pragma unroll
                for (int n = 0; n < 8; n++) mma_bf16(acc[m][n], ah[m], bh[n]);
            #pragma unroll
            for (int m = 0; m < 4; m++)
                #pragma unroll
                for (int n = 0; n < 8; n++) mma_bf16(acc[m][n], ah[m], bl[n]);
            #pragma unroll
            for (int m = 0; m < 4; m++)
                #pragma unroll
                for (int n = 0; n < 8; n++) mma_bf16(acc[m][n], al[m], bh[n]);
        }
        sc = (sc == 2) ? 0 : sc + 1;
        scn = (scn == 2) ? 0 : scn + 1;
    }

    // ---- epilogue ----
    const int g = lane >> 2, q = lane & 3;
    #pragma unroll
    for (int m = 0; m < 4; m++) {
        #pragma unroll
        for (int n = 0; n < 8; n++) {
            int col = bn + warpN * 64 + n * 8 + 2 * q;
            float b0 = bias ? bias[col] : 0.f;
            float b1 = bias ? bias[col + 1] : 0.f;
            #pragma unroll
            for (int hrow = 0; hrow < 2; hrow++) {
                int row = bm + warpM * 64 + m * 16 + g + hrow * 8;
                float v0 = acc[m][n][hrow * 2 + 0] + b0;
                float v1 = acc[m][n][hrow * 2 + 1] + b1;
                if (ACT == 1) {
                    v0 = v0 * 0.5f * (1.f + erff(v0 * 0.7071067811865476f));
                    v1 = v1 * 0.5f * (1.f + erff(v1 * 0.7071067811865476f));
                }
                if (OUTMODE == 0) {
                    *(float2*)(Cf + (size_t)row * Ntot + col) = make_float2(v0, v1);
                } else {
                    __nv_bfloat16 h0 = __float2bfloat16(v0);
                    __nv_bfloat16 h1 = __float2bfloat16(v1);
                    *(uint32_t*)(Ch + (size_t)row * Ntot + col) =
                        (uint32_t)__bfloat16_as_ushort(h0) |
                        ((uint32_t)__bfloat16_as_ushort(h1) << 16);
                    *(uint32_t*)(Cl + (size_t)row * Ntot + col) =
                        pack_bf2(v0 - __bfloat162float(h0), v1 - __bfloat162float(h1));
                }
            }
        }
    }
}

// ================= window attention (emits bf16 hi/lo) =================
__global__ void __launch_bounds__(256)
attn_kernel(const float* __restrict__ qkv, const float* __restrict__ tau,
            const float* __restrict__ cpb, __nv_bfloat16* __restrict__ outh,
            __nv_bfloat16* __restrict__ outl, int shifted) {
    __shared__ float sq[64 * 33];
    __shared__ float sk[64 * 33];
    __shared__ float sv[49 * 33];
    __shared__ float sd[64 * 52];

    const int wi   = blockIdx.x;
    const int head = blockIdx.y;
    const int b    = blockIdx.z;
    const int wh = wi >> 3, ww = wi & 7;
    const int tid = threadIdx.x;

    for (int e = tid; e < 64 * 32; e += 256) {
        int r = e >> 5, d = e & 31;
        if (r < WIN2) {
            int i = r / WIN, j = r % WIN;
            int m = b * Nn + (wh * WIN + i) * Wd + (ww * WIN + j);
            const float* base = qkv + (size_t)m * 768 + head * HD + d;
            sq[r * 33 + d] = base[0];
            sk[r * 33 + d] = base[256];
            sv[r * 33 + d] = base[512];
        } else {
            sq[r * 33 + d] = 0.f;
            sk[r * 33 + d] = 0.f;
        }
    }
    __syncthreads();

    for (int t = tid; t < 2 * WIN2; t += 256) {
        float* row = (t < WIN2) ? (sq + t * 33) : (sk + (t - WIN2) * 33);
        float s = 0.f;
        #pragma unroll
        for (int d = 0; d < HD; d++) s += row[d] * row[d];
        float inv = 1.f / fmaxf(sqrtf(s), 1e-12f);
        #pragma unroll
        for (int d = 0; d < HD; d++) row[d] *= inv;
    }
    __syncthreads();

    const float tscale = 1.f / fmaxf(tau[head], 0.01f);
    const int tx = tid & 15, ty = tid >> 4;

    float acc[4][4];
    #pragma unroll
    for (int u = 0; u < 4; u++)
        #pragma unroll
        for (int v = 0; v < 4; v++) acc[u][v] = 0.f;
    #pragma unroll
    for (int kk = 0; kk < HD; kk++) {
        float a[4], bb[4];
        #pragma unroll
        for (int u = 0; u < 4; u++) a[u]  = sq[(ty + u * 16) * 33 + kk];
        #pragma unroll
        for (int v = 0; v < 4; v++) bb[v] = sk[(tx + v * 16) * 33 + kk];
        #pragma unroll
        for (int u = 0; u < 4; u++)
            #pragma unroll
            for (int v = 0; v < 4; v++) acc[u][v] += a[u] * bb[v];
    }
    #pragma unroll
    for (int u = 0; u < 4; u++) {
        int i = ty + u * 16;
        if (i >= WIN2) continue;
        #pragma unroll
        for (int v = 0; v < 4; v++) {
            int j = tx + v * 16;
            if (j >= WIN2) continue;
            float val = acc[u][v] * tscale + cpb[head * (WIN2 * WIN2) + i * WIN2 + j];
            if (shifted) {
                if (wh == NWH - 1 && ((i >= 28) != (j >= 28))) val = -1e30f;
                if (ww == NWH - 1 && (((i % WIN) >= 4) != ((j % WIN) >= 4))) val = -1e30f;
            }
            sd[i * 52 + j] = val;
        }
    }
    __syncthreads();

    const int lane = tid & 31, wrp = tid >> 5;
    for (int r = wrp; r < WIN2; r += 8) {
        float v0 = sd[r * 52 + lane];
        float v1 = (lane + 32 < WIN2) ? sd[r * 52 + lane + 32] : -3e38f;
        float mx = fmaxf(v0, v1);
        #pragma unroll
        for (int o = 16; o > 0; o >>= 1) mx = fmaxf(mx, __shfl_xor_sync(~0u, mx, o));
        float e0 = __expf(v0 - mx);
        float e1 = (lane + 32 < WIN2) ? __expf(v1 - mx) : 0.f;
        float s = e0 + e1;
        #pragma unroll
        for (int o = 16; o > 0; o >>= 1) s += __shfl_xor_sync(~0u, s, o);
        float inv = 1.f / s;
        sd[r * 52 + lane] = e0 * inv;
        if (lane + 32 < WIN2) sd[r * 52 + lane + 32] = e1 * inv;
    }
    __syncthreads();

    float o2[4][2];
    #pragma unroll
    for (int u = 0; u < 4; u++) { o2[u][0] = 0.f; o2[u][1] = 0.f; }
    for (int j = 0; j < WIN2; j++) {
        float p[4];
        #pragma unroll
        for (int u = 0; u < 4; u++) p[u] = sd[(ty + u * 16) * 52 + j];
        float v0 = sv[j * 33 + tx * 2];
        float v1 = sv[j * 33 + tx * 2 + 1];
        #pragma unroll
        for (int u = 0; u < 4; u++) {
            o2[u][0] += p[u] * v0;
            o2[u][1] += p[u] * v1;
        }
    }
    #pragma unroll
    for (int u = 0; u < 4; u++) {
        int i = ty + u * 16;
        if (i < WIN2) {
            int ii = i / WIN, jj = i % WIN;
            int m = b * Nn + (wh * WIN + ii) * Wd + (ww * WIN + jj);
            size_t off = (size_t)m * Dd + head * HD + tx * 2;
            __nv_bfloat16 h0 = __float2bfloat16(o2[u][0]);
            __nv_bfloat16 h1 = __float2bfloat16(o2[u][1]);
            *(uint32_t*)(outh + off) = (uint32_t)__bfloat16_as_ushort(h0) |
                                       ((uint32_t)__bfloat16_as_ushort(h1) << 16);
            *(uint32_t*)(outl + off) = pack_bf2(o2[u][0] - __bfloat162float(h0),
                                                o2[u][1] - __bfloat162float(h1));
        }
    }
}

// ================= LN + residual =================
__global__ void ln_residual_kernel(const float* __restrict__ A, const float* __restrict__ g,
                                   const float* __restrict__ be, float* __restrict__ xm,
                                   __nv_bfloat16* __restrict__ xh, __nv_bfloat16* __restrict__ xl,
                                   int gather) {
    int row = blockIdx.x * 8 + (threadIdx.x >> 5);
    int lane = threadIdx.x & 31;
    int src = row;
    if (gather) {
        int b = row / Nn, rem = row % Nn;
        int h = rem / Wd, w = rem % Wd;
        src = b * Nn + ((h + Hh - DISP) % Hh) * Wd + ((w + Wd - DISP) % Wd);
    }
    const float4* a4 = (const float4*)(A + (size_t)src * Dd);
    float4 v0 = a4[lane], v1 = a4[lane + 32];
    float s  = v0.x + v0.y + v0.z + v0.w + v1.x + v1.y + v1.z + v1.w;
    float s2 = v0.x*v0.x + v0.y*v0.y + v0.z*v0.z + v0.w*v0.w
             + v1.x*v1.x + v1.y*v1.y + v1.z*v1.z + v1.w*v1.w;
    #pragma unroll
    for (int o = 16; o > 0; o >>= 1) {
        s  += __shfl_xor_sync(~0u, s, o);
        s2 += __shfl_xor_sync(~0u, s2, o);
    }
    float mean = s * (1.f / Dd);
    float var  = s2 * (1.f / Dd) - mean * mean;
    float inv  = rsqrtf(var + EPSLN);

    float4 g0 = ((const float4*)g)[lane],  g1 = ((const float4*)g)[lane + 32];
    float4 b0 = ((const float4*)be)[lane], b1 = ((const float4*)be)[lane + 32];
    float4* x4 = (float4*)(xm + (size_t)row * Dd);
    float4 r0 = x4[lane], r1 = x4[lane + 32];
    r0.x += (v0.x - mean) * inv * g0.x + b0.x;
    r0.y += (v0.y - mean) * inv * g0.y + b0.y;
    r0.z += (v0.z - mean) * inv * g0.z + b0.z;
    r0.w += (v0.w - mean) * inv * g0.w + b0.w;
    r1.x += (v1.x - mean) * inv * g1.x + b1.x;
    r1.y += (v1.y - mean) * inv * g1.y + b1.y;
    r1.z += (v1.z - mean) * inv * g1.z + b1.z;
    r1.w += (v1.w - mean) * inv * g1.w + b1.w;
    x4[lane] = r0; x4[lane + 32] = r1;

    uint2 h, l;
    size_t e0 = (size_t)row * Dd + lane * 4;
    size_t e1 = e0 + 128;
    split_f4(r0, h, l);
    *(uint2*)(xh + e0) = h; *(uint2*)(xl + e0) = l;
    split_f4(r1, h, l);
    *(uint2*)(xh + e1) = h; *(uint2*)(xl + e1) = l;
}

// ================= final LN =================
__global__ void ln_final_kernel(const float* __restrict__ A, const float* __restrict__ g,
                                const float* __restrict__ be, float* __restrict__ out) {
    int row = blockIdx.x * 8 + (threadIdx.x >> 5);
    int lane = threadIdx.x & 31;
    const float4* a4 = (const float4*)(A + (size_t)row * Dd);
    float4 v0 = a4[lane], v1 = a4[lane + 32];
    float s  = v0.x + v0.y + v0.z + v0.w + v1.x + v1.y + v1.z + v1.w;
    float s2 = v0.x*v0.x + v0.y*v0.y + v0.z*v0.z + v0.w*v0.w
             + v1.x*v1.x + v1.y*v1.y + v1.z*v1.z + v1.w*v1.w;
    #pragma unroll
    for (int o = 16; o > 0; o >>= 1) {
        s  += __shfl_xor_sync(~0u, s, o);
        s2 += __shfl_xor_sync(~0u, s2, o);
    }
    float mean = s * (1.f / Dd);
    float var  = s2 * (1.f / Dd) - mean * mean;
    float inv  = rsqrtf(var + EPSLN);
    float4 g0 = ((const float4*)g)[lane],  g1 = ((const float4*)g)[lane + 32];
    float4 b0 = ((const float4*)be)[lane], b1 = ((const float4*)be)[lane + 32];
    float4 o0, o1;
    o0.x = (v0.x - mean) * inv * g0.x + b0.x;
    o0.y = (v0.y - mean) * inv * g0.y + b0.y;
    o0.z = (v0.z - mean) * inv * g0.z + b0.z;
    o0.w = (v0.w - mean) * inv * g0.w + b0.w;
    o1.x = (v1.x - mean) * inv * g1.x + b1.x;
    o1.y = (v1.y - mean) * inv * g1.y + b1.y;
    o1.z = (v1.z - mean) * inv * g1.z + b1.z;
    o1.w = (v1.w - mean) * inv * g1.w + b1.w;
    float4* out4 = (float4*)(out + (size_t)row * Dd);
    out4[lane] = o0; out4[lane + 32] = o1;
}

// ================= launch =================
extern "C" void kernel_launch(void* const* d_in, const int* in_sizes, int n_in,
                              void* d_out, int out_size) {
    const float* x    = (const float*)d_in[0];
    const float* spe  = (const float*)d_in[1];
    const float* qkvw = (const float*)d_in[2];
    const float* tau  = (const float*)d_in[3];
    const float* cw1  = (const float*)d_in[4];
    const float* cb1  = (const float*)d_in[5];
    const float* cw2  = (const float*)d_in[6];
    const float* cb2  = (const float*)d_in[7];
    const float* ow   = (const float*)d_in[8];
    const float* ob   = (const float*)d_in[9];
    const float* ln1g = (const float*)d_in[10];
    const float* ln1b = (const float*)d_in[11];
    const float* fw1  = (const float*)d_in[12];
    const float* fb1  = (const float*)d_in[13];
    const float* fw2  = (const float*)d_in[14];
    const float* fb2  = (const float*)d_in[15];
    const float* ln2g = (const float*)d_in[16];
    const float* ln2b = (const float*)d_in[17];
    const float* ng   = (const float*)d_in[18];
    const float* nb   = (const float*)d_in[19];
    float* out = (float*)d_out;

    float *xm, *qkv, *tmp, *cpb;
    __nv_bfloat16 *xmh, *xml, *ath, *atl, *ffh, *ffl, *wth, *wtl;
    cudaGetSymbolAddress((void**)&xm,  g_xm);
    cudaGetSymbolAddress((void**)&qkv, g_qkv);
    cudaGetSymbolAddress((void**)&tmp, g_tmp);
    cudaGetSymbolAddress((void**)&cpb, g_cpb);
    cudaGetSymbolAddress((void**)&xmh, g_xmh);
    cudaGetSymbolAddress((void**)&xml, g_xml);
    cudaGetSymbolAddress((void**)&ath, g_ath);
    cudaGetSymbolAddress((void**)&atl, g_atl);
    cudaGetSymbolAddress((void**)&ffh, g_ffh);
    cudaGetSymbolAddress((void**)&ffl, g_ffl);
    cudaGetSymbolAddress((void**)&wth, g_wth);
    cudaGetSymbolAddress((void**)&wtl, g_wtl);

    cudaFuncSetAttribute(hgemm_kernel<0, false, 0>, cudaFuncAttributeMaxDynamicSharedMemorySize, GEMM_SMEM);
    cudaFuncSetAttribute(hgemm_kernel<0, true,  0>, cudaFuncAttributeMaxDynamicSharedMemorySize, GEMM_SMEM);
    cudaFuncSetAttribute(hgemm_kernel<1, false, 1>, cudaFuncAttributeMaxDynamicSharedMemorySize, GEMM_SMEM);

    // weight transpose + bf16 split (both layers)
    for (int l = 0; l < 2; l++) {
        size_t wo = (size_t)l * WLSTRIDE;
        wtconv_kernel<<<dim3(768 / 32, 256 / 32), dim3(32, 8)>>>(
            qkvw + (size_t)l * Dd * 768, wth + wo, wtl + wo, 256, 768);
        wtconv_kernel<<<dim3(256 / 32, 256 / 32), dim3(32, 8)>>>(
            ow + (size_t)l * Dd * Dd, wth + wo + 196608, wtl + wo + 196608, 256, 256);
        wtconv_kernel<<<dim3(1024 / 32, 256 / 32), dim3(32, 8)>>>(
            fw1 + (size_t)l * Dd * FF, wth + wo + 262144, wtl + wo + 262144, 256, 1024);
        wtconv_kernel<<<dim3(256 / 32, 1024 / 32), dim3(32, 8)>>>(
            fw2 + (size_t)l * FF * Dd, wth + wo + 524288, wtl + wo + 524288, 1024, 256);
    }

    // xm = x + spe (+ bf16 split)
    {
        int n4 = MROWS * Dd / 4;
        add_spe_kernel<<<(n4 + 255) / 256, 256>>>(x, spe, xm, xmh, xml, n4);
    }

    const int lnBlocks = MROWS / 8;
    const int MT = MROWS / 256;   // 196
    for (int layer = 0; layer < 2; layer++) {
        int shifted = (layer == 1);
        size_t wo = (size_t)layer * WLSTRIDE;

        cpb_kernel<<<WIN2 * WIN2, 256>>>(cw1 + layer * 2 * CPBH, cb1 + layer * CPBH,
                                         cw2 + layer * CPBH * HEADS, cb2 + layer * HEADS, cpb);

        // qkv = (rolled) xm @ qkv_w -> fp32
        if (shifted)
            hgemm_kernel<0, true, 0><<<dim3(6, MT), 256, GEMM_SMEM>>>(
                xmh, xml, wth + wo, wtl + wo, nullptr, qkv, nullptr, nullptr, 768, 256);
        else
            hgemm_kernel<0, false, 0><<<dim3(6, MT), 256, GEMM_SMEM>>>(
                xmh, xml, wth + wo, wtl + wo, nullptr, qkv, nullptr, nullptr, 768, 256);

        attn_kernel<<<dim3(NW, HEADS, Bb), 256>>>(qkv, tau + layer * HEADS, cpb, ath, atl, shifted);

        // o-proj -> tmp (fp32)
        hgemm_kernel<0, false, 0><<<dim3(2, MT), 256, GEMM_SMEM>>>(
            ath, atl, wth + wo + 196608, wtl + wo + 196608, ob + layer * Dd,
            tmp, nullptr, nullptr, 256, 256);

        // xm += LN(oproj) (rolled back if shifted)
        ln_residual_kernel<<<lnBlocks, 256>>>(tmp, ln1g + layer * Dd, ln1b + layer * Dd,
                                              xm, xmh, xml, shifted);

        // ffn1: gelu(xm @ fw1 + fb1) -> bf16 hi/lo
        hgemm_kernel<1, false, 1><<<dim3(8, MT), 256, GEMM_SMEM>>>(
            xmh, xml, wth + wo + 262144, wtl + wo + 262144, fb1 + layer * FF,
            nullptr, ffh, ffl, 1024, 256);

        // ffn2 -> tmp (fp32)
        hgemm_kernel<0, false, 0><<<dim3(2, MT), 256, GEMM_SMEM>>>(
            ffh, ffl, wth + wo + 524288, wtl + wo + 524288, fb2 + layer * Dd,
            tmp, nullptr, nullptr, 256, 1024);

        // xm += LN(ffn2)
        ln_residual_kernel<<<lnBlocks, 256>>>(tmp, ln2g + layer * Dd, ln2b + layer * Dd,
                                              xm, xmh, xml, 0);
    }

    ln_final_kernel<<<lnBlocks, 256>>>(xm, ng, nb, out);
}